// round 13
// baseline (speedup 1.0000x reference)
#include <cuda_runtime.h>
#include <cuda_fp16.h>
#include <cstdint>
#include <math.h>

#define B_TOT 65536
#define EPS 1e-5f
#define NXF (65536 * 256)          // floats per X plane
#define NWF (1024 * 256)           // floats per W plane

// ---------------- scratch (static device globals; no runtime alloc) ----------
__device__ __half g_Kh[(size_t)B_TOT * 2048];          // 256 MB (fp16 K)
__device__ __half g_Vh[(size_t)B_TOT * 2048];          // 256 MB (fp16 V)
__device__ __half g_Xh[(size_t)2 * NXF];               // 64 MB (fp16 X)
__device__ __half g_Wh[(size_t)4 * NWF];               // 2 MB (fp16 W)
__device__ float g_sumK[64];
__device__ float g_sumK2[64];
__device__ float g_cmd[20];
__device__ float g_cst[256];

// ================= PTX helpers (sm_80-era; safe on plain sm_103) =============
__device__ __forceinline__ uint32_t smem_u32(const void* p) {
    uint32_t a;
    asm("{ .reg .u64 t; cvta.to.shared.u64 t, %1; cvt.u32.u64 %0, t; }" : "=r"(a) : "l"(p));
    return a;
}
#define CP16(dst, src) \
    asm volatile("cp.async.cg.shared.global [%0], [%1], 16;" :: "r"(dst), "l"(src))
#define CP_COMMIT() asm volatile("cp.async.commit_group;")
#define CP_WAIT2()  asm volatile("cp.async.wait_group 2;")
#define CP_WAIT1()  asm volatile("cp.async.wait_group 1;")
#define CP_WAIT0()  asm volatile("cp.async.wait_group 0;")

#define LDSM4(r0, r1, r2, r3, addr) \
    asm volatile("ldmatrix.sync.aligned.m8n8.x4.shared.b16 {%0,%1,%2,%3}, [%4];" \
                 : "=r"(r0), "=r"(r1), "=r"(r2), "=r"(r3) : "r"(addr))

#define MMA16816(d, a, b0, b1) \
    asm volatile("mma.sync.aligned.m16n8k16.row.col.f32.f16.f16.f32 " \
                 "{%0,%1,%2,%3},{%4,%5,%6,%7},{%8,%9},{%0,%1,%2,%3};" \
                 : "+f"((d)[0]), "+f"((d)[1]), "+f"((d)[2]), "+f"((d)[3]) \
                 : "r"((a)[0]), "r"((a)[1]), "r"((a)[2]), "r"((a)[3]), \
                   "r"(b0), "r"(b1))

// ---------------- zero the accumulators --------------------------------------
__global__ void zero_stats_kernel() {
    int t = threadIdx.x;
    if (t < 64) { g_sumK[t] = 0.f; g_sumK2[t] = 0.f; }
    if (t < 20) { g_cmd[t] = 0.f; }
}

// ---------------- command column sums + 4x4 Gram ------------------------------
__global__ void cmd_stats_kernel(const float* __restrict__ command) {
    float s[4]  = {0.f, 0.f, 0.f, 0.f};
    float g[16] = {0.f};
    int stride = gridDim.x * blockDim.x;
    for (int b = blockIdx.x * blockDim.x + threadIdx.x; b < B_TOT; b += stride) {
        float4 c = *(const float4*)(command + (size_t)b * 4);
        float v[4] = {c.x, c.y, c.z, c.w};
        #pragma unroll
        for (int i = 0; i < 4; i++) {
            s[i] += v[i];
            #pragma unroll
            for (int j = 0; j < 4; j++) g[i * 4 + j] += v[i] * v[j];
        }
    }
    __shared__ float sh[20];
    if (threadIdx.x < 20) sh[threadIdx.x] = 0.f;
    __syncthreads();
    #pragma unroll
    for (int i = 0; i < 4; i++) atomicAdd(&sh[i], s[i]);
    #pragma unroll
    for (int i = 0; i < 16; i++) atomicAdd(&sh[4 + i], g[i]);
    __syncthreads();
    if (threadIdx.x < 20) atomicAdd(&g_cmd[threadIdx.x], sh[threadIdx.x]);
}

// ---------------- convert X and W to fp16 -------------------------------------
__global__ __launch_bounds__(256) void split_kernel(
    const float* __restrict__ f, const float* __restrict__ h,
    const float* __restrict__ wkz, const float* __restrict__ wkh,
    const float* __restrict__ wvz, const float* __restrict__ wvh)
{
    const size_t NX4 = (size_t)2 * NXF / 4;
    size_t gid = (size_t)blockIdx.x * 256 + threadIdx.x;

    const float* src;
    __half* dst;
    size_t base;
    if (gid < NX4) {
        base = gid * 4;
        src = (base < (size_t)NXF) ? (f + base) : (h + (base - NXF));
        dst = g_Xh + base;
    } else {
        base = (gid - NX4) * 4;
        size_t o = base;
        if      (o < (size_t)NWF)       src = wkz + o;
        else if (o < (size_t)2 * NWF)   src = wkh + (o - NWF);
        else if (o < (size_t)3 * NWF)   src = wvz + (o - 2 * (size_t)NWF);
        else                            src = wvh + (o - 3 * (size_t)NWF);
        dst = g_Wh + base;
    }
    float4 v = *(const float4*)src;
    float vv[4] = {v.x, v.y, v.z, v.w};
    ushort4 uh;
    unsigned short* ph = (unsigned short*)&uh;
    #pragma unroll
    for (int i = 0; i < 4; i++)
        ph[i] = __half_as_ushort(__float2half_rn(vv[i]));
    *(ushort4*)dst = uh;
}

// =============================================================================
// HMMA fp16 GEMM, B-RESIDENT, 2 CTAs/SM, kc-unrolled, pad-80B A stages.
// 2048 CTAs x 256 threads (8 warps, warp tile 32x64).
//   combo = blk & 31 -> which = combo & 3, coltile = combo >> 2 (0..7)
//   rg    = blk >> 5 -> row blocks rg*8 .. rg*8+7 (128 rows each)
// B tile (128 cols x 256 K fp16 = 64KB) resident.
// A streamed: per block 8 K-chunks of 32 (8KB data in 10KB padded stage),
// 4-stage ring with stage == kc&3 (compile-time). A rows padded to 80B ->
// conflict-free LDSM with NO xor swizzle.
// smem: B 65536 | A 4*10240 = 106496 bytes (2 CTAs = 212992 <= 227328).
// =============================================================================
#define B_RES   65536
#define ASTG    10240
#define GEMM_SMEM (B_RES + 4 * ASTG)

__global__ __launch_bounds__(256, 2) void gemm_mma_kernel()
{
    extern __shared__ char sm[];
    const uint32_t sb = smem_u32(sm);
    __shared__ float sd[64], sd2[64];

    const int tid  = threadIdx.x;
    const int warp = tid >> 5;
    const int lane = tid & 31;
    const int wm   = (warp >> 1) * 32;     // warp M origin 0..96
    const int wn   = (warp & 1) * 64;      // warp N origin 0 or 64

    const int blk     = blockIdx.x;
    const int combo   = blk & 31;
    const int which   = combo & 3;
    const int coltile = combo >> 2;        // 0..7
    const int rg      = blk >> 5;          // 0..63
    const int col0    = coltile * 128;
    const int jb      = (which & 1) * 1024;
    const int p       = which & 1;

    const __half* __restrict__ Xh = g_Xh + (size_t)p * NXF;
    const __half* __restrict__ Wc = g_Wh + (size_t)which * NWF;

    if (tid < 64) { sd[tid] = 0.f; sd2[tid] = 0.f; }

    float acc[2][8][4];
    #pragma unroll
    for (int a = 0; a < 2; a++)
        #pragma unroll
        for (int b = 0; b < 8; b++)
            #pragma unroll
            for (int c = 0; c < 4; c++) acc[a][b][c] = 0.f;

    // ---- B resident load: 128 rows x 512B; thread -> row tid>>1, 16 chunks ---
    {
        const int n   = tid >> 1;
        const int c0  = (tid & 1) * 16;
        const __half* s0 = Wc + (size_t)(col0 + n) * 256;
        const uint32_t nb = sb + n * 512;
        #pragma unroll
        for (int q = 0; q < 16; q++) {
            int ch = c0 + q;
            uint32_t sw = (uint32_t)((ch & 24) | ((ch ^ (n & 7)) & 7)) << 4;
            CP16(nb + sw, s0 + ch * 8);
        }
    }
    CP_COMMIT();   // group: B

    // ---- A chunk issue (kcL compile-time at call sites); K-chunk = 32 --------
    // 128 rows x 64B data, padded to 80B rows in smem (conflict-free LDSM).
    auto issueA = [&](int block, int kcL) {
        const int rowg  = (rg * 8 + block) * 128;
        const int r     = tid >> 1;            // 0..127
        const int c0    = (tid & 1) * 2;       // chunk pair 0-1 or 2-3
        const __half* s0 = Xh + (size_t)(rowg + r) * 256 + kcL * 32 + c0 * 8;
        const uint32_t rb = sb + B_RES + (kcL & 3) * ASTG + r * 80 + c0 * 16;
        CP16(rb,      s0);
        CP16(rb + 16, s0 + 8);
    };

    issueA(0, 0); CP_COMMIT();
    issueA(0, 1); CP_COMMIT();
    issueA(0, 2); CP_COMMIT();

    const int rlo   = lane >> 2;
    const int cpair = (lane & 3) * 2;
    const int lrow  = lane & 15;
    const int lhalf = lane >> 4;

    __half* C = (which < 2) ? g_Kh : g_Vh;
    const bool dostats = (which < 2);

    for (int blkI = 0; blkI < 8; blkI++) {
        #pragma unroll
        for (int kc = 0; kc < 8; kc++) {
            const int g = blkI * 8 + kc;
            {
                int rem = 63 - g;
                if (rem >= 2)      { CP_WAIT2(); }
                else if (rem == 1) { CP_WAIT1(); }
                else               { CP_WAIT0(); }
            }
            __syncthreads();
            {
                const int kcN  = (kc + 3) & 7;
                const int blkN = blkI + (kc >= 5 ? 1 : 0);
                if (blkN < 8) { issueA(blkN, kcN); CP_COMMIT(); }
            }

            const uint32_t astg = sb + B_RES + (kc & 3) * ASTG;  // literal

            #pragma unroll
            for (int k16 = 0; k16 < 2; k16++) {
                uint32_t ah[2][4];
                #pragma unroll
                for (int mf = 0; mf < 2; mf++) {
                    int r = wm + mf * 16 + lrow;
                    uint32_t ad = astg + r * 80 + (uint32_t)(k16 * 2 + lhalf) * 16;
                    LDSM4(ah[mf][0], ah[mf][1], ah[mf][2], ah[mf][3], ad);
                }
                #pragma unroll
                for (int j = 0; j < 4; j++) {
                    int n  = wn + j * 16 + lrow;
                    int ch = kc * 4 + k16 * 2 + lhalf;    // literal kc,k16
                    uint32_t sw = (uint32_t)((ch & 24) | ((ch ^ (n & 7)) & 7)) << 4;
                    uint32_t bd = sb + n * 512 + sw;
                    uint32_t b0, b1, b2, b3;
                    LDSM4(b0, b1, b2, b3, bd);
                    #pragma unroll
                    for (int mf = 0; mf < 2; mf++) {
                        MMA16816(acc[mf][2 * j],     ah[mf], b0, b2);
                        MMA16816(acc[mf][2 * j + 1], ah[mf], b1, b3);
                    }
                }
            }
        }

        // -------- block epilogue: fp16 direct store + (K combos) stats --------
        {
            const int rowg = (rg * 8 + blkI) * 128;
            #pragma unroll
            for (int mf = 0; mf < 2; mf++) {
                #pragma unroll
                for (int nf = 0; nf < 8; nf++) {
                    int row = rowg + wm + mf * 16 + rlo;
                    int col = jb + col0 + wn + nf * 8 + cpair;
                    *(__half2*)(C + (size_t)row * 2048 + col) =
                        __floats2half2_rn(acc[mf][nf][0], acc[mf][nf][1]);
                    *(__half2*)(C + (size_t)(row + 8) * 2048 + col) =
                        __floats2half2_rn(acc[mf][nf][2], acc[mf][nf][3]);
                }
            }
            if (dostats) {
                #pragma unroll
                for (int nf = 0; nf < 8; nf++) {
                    float s0 = 0.f, s1 = 0.f, q0 = 0.f, q1 = 0.f;
                    #pragma unroll
                    for (int mf = 0; mf < 2; mf++) {
                        float a0 = acc[mf][nf][0], a1 = acc[mf][nf][1];
                        float a2 = acc[mf][nf][2], a3 = acc[mf][nf][3];
                        s0 += a0 + a2;  s1 += a1 + a3;
                        q0 += a0 * a0 + a2 * a2;
                        q1 += a1 * a1 + a3 * a3;
                    }
                    #pragma unroll
                    for (int o = 4; o <= 16; o <<= 1) {
                        s0 += __shfl_xor_sync(0xffffffffu, s0, o);
                        s1 += __shfl_xor_sync(0xffffffffu, s1, o);
                        q0 += __shfl_xor_sync(0xffffffffu, q0, o);
                        q1 += __shfl_xor_sync(0xffffffffu, q1, o);
                    }
                    if (lane < 4) {
                        int d = (wn + nf * 8 + lane * 2) & 63;
                        atomicAdd(&sd[d], s0);   atomicAdd(&sd[d + 1], s1);
                        atomicAdd(&sd2[d], q0);  atomicAdd(&sd2[d + 1], q1);
                    }
                }
            }
            #pragma unroll
            for (int a = 0; a < 2; a++)
                #pragma unroll
                for (int b = 0; b < 8; b++)
                    #pragma unroll
                    for (int c2 = 0; c2 < 4; c2++) acc[a][b][c2] = 0.f;
        }
    }

    __syncthreads();
    if (dostats && tid < 64) {
        atomicAdd(&g_sumK[tid], sd[tid]);
        atomicAdd(&g_sumK2[tid], sd2[tid]);
    }
}

// ---------------- fold BN stats into per-d affine constants ------------------
__global__ void finalize_kernel(const float* __restrict__ Wq,
                                const float* __restrict__ gammaQ,
                                const float* __restrict__ betaQ,
                                const float* __restrict__ gammaK,
                                const float* __restrict__ betaK)
{
    int d = threadIdx.x;
    if (d >= 64) return;
    const float invB = 1.f / 65536.f;

    float w[4];
    #pragma unroll
    for (int c = 0; c < 4; c++) w[c] = Wq[d * 4 + c];

    float mQ = 0.f;
    #pragma unroll
    for (int c = 0; c < 4; c++) mQ += (g_cmd[c] * invB) * w[c];
    float eq2 = 0.f;
    #pragma unroll
    for (int c1 = 0; c1 < 4; c1++)
        #pragma unroll
        for (int c2 = 0; c2 < 4; c2++)
            eq2 += w[c1] * w[c2] * g_cmd[4 + c1 * 4 + c2];
    eq2 *= invB;
    float vQ = eq2 - mQ * mQ;
    float gq = gammaQ[d] / sqrtf(vQ + EPS);
    g_cst[d]      = gq;
    g_cst[64 + d] = betaQ[d] - mQ * gq;

    const float invBF = 1.f / (65536.f * 32.f);
    float mK = g_sumK[d] * invBF;
    float vK = g_sumK2[d] * invBF - mK * mK;
    float aK = gammaK[d] / sqrtf(vK + EPS);
    g_cst[128 + d] = aK;
    g_cst[192 + d] = betaK[d] - mK * aK;
}

// ---------------- attention: 1 warp per batch row, coalesced K ----------------
__global__ __launch_bounds__(256) void attn_kernel(
    const float* __restrict__ command, const float* __restrict__ Wq,
    float* __restrict__ out)
{
    const int w    = threadIdx.x >> 5;
    const int lane = threadIdx.x & 31;
    const int b    = blockIdx.x * 8 + w;

    float4 c4 = *(const float4*)(command + (size_t)b * 4);
    const int d0 = 2 * lane, d1 = 2 * lane + 1;

    float q0 = c4.x * Wq[d0 * 4 + 0] + c4.y * Wq[d0 * 4 + 1] +
               c4.z * Wq[d0 * 4 + 2] + c4.w * Wq[d0 * 4 + 3];
    float q1 = c4.x * Wq[d1 * 4 + 0] + c4.y * Wq[d1 * 4 + 1] +
               c4.z * Wq[d1 * 4 + 2] + c4.w * Wq[d1 * 4 + 3];
    float qn0 = q0 * g_cst[d0] + g_cst[64 + d0];
    float qn1 = q1 * g_cst[d1] + g_cst[64 + d1];

    float qa0 = qn0 * g_cst[128 + d0];
    float qa1 = qn1 * g_cst[128 + d1];
    float qc  = qn0 * g_cst[192 + d0] + qn1 * g_cst[192 + d1];
    #pragma unroll
    for (int o = 16; o; o >>= 1) qc += __shfl_xor_sync(0xffffffffu, qc, o);

    // per-f partials over this lane's d-pair (coalesced 128B per f)
    const __half2* Kr = (const __half2*)(g_Kh + (size_t)b * 2048) + lane;
    float p[32];
    #pragma unroll
    for (int f = 0; f < 32; f++) {
        float2 kf = __half22float2(Kr[f * 32]);
        p[f] = qa0 * kf.x + qa1 * kf.y;
    }

    // butterfly transpose-reduce: lane l ends with full logit for f = l
    #pragma unroll
    for (int o = 16; o >= 1; o >>= 1) {
        #pragma unroll
        for (int j = 0; j < o; j++) {
            bool hi = (lane & o) != 0;
            float keep = hi ? p[j + o] : p[j];
            float send = hi ? p[j] : p[j + o];
            p[j] = keep + __shfl_xor_sync(0xffffffffu, send, o);
        }
    }
    float logit = (p[0] + qc) * 0.125f;   // 1/sqrt(64)

    float mx = logit;
    #pragma unroll
    for (int o = 16; o; o >>= 1) mx = fmaxf(mx, __shfl_xor_sync(0xffffffffu, mx, o));
    float e = __expf(logit - mx);
    float den = e;
    #pragma unroll
    for (int o = 16; o; o >>= 1) den += __shfl_xor_sync(0xffffffffu, den, o);
    float a = e / den;

    const __half2* Vr = (const __half2*)(g_Vh + (size_t)b * 2048);
    float s0 = 0.f, s1 = 0.f;
    #pragma unroll
    for (int f = 0; f < 32; f++) {
        float af = __shfl_sync(0xffffffffu, a, f);
        float2 vf = __half22float2(Vr[f * 32 + lane]);
        s0 += af * vf.x;
        s1 += af * vf.y;
    }
    *(float2*)(out + (size_t)b * 64 + 2 * lane) = make_float2(s0, s1);
}

// ---------------- launch ------------------------------------------------------
extern "C" void kernel_launch(void* const* d_in, const int* in_sizes, int n_in,
                              void* d_out, int out_size)
{
    const float* feature = (const float*)d_in[0];
    const float* hidden  = (const float*)d_in[1];
    const float* command = (const float*)d_in[2];
    const float* Wq      = (const float*)d_in[3];
    const float* Wkz     = (const float*)d_in[4];
    const float* Wkh     = (const float*)d_in[5];
    const float* Wvz     = (const float*)d_in[6];
    const float* Wvh     = (const float*)d_in[7];
    const float* gammaQ  = (const float*)d_in[8];
    const float* betaQ   = (const float*)d_in[9];
    const float* gammaK  = (const float*)d_in[10];
    const float* betaK   = (const float*)d_in[11];
    float* out = (float*)d_out;

    cudaFuncSetAttribute(gemm_mma_kernel,
                         cudaFuncAttributeMaxDynamicSharedMemorySize, GEMM_SMEM);

    zero_stats_kernel<<<1, 64>>>();
    cmd_stats_kernel<<<128, 256>>>(command);
    split_kernel<<<33792, 256>>>(feature, hidden, Wkz, Wkh, Wvz, Wvh);
    gemm_mma_kernel<<<2048, 256, GEMM_SMEM>>>();
    finalize_kernel<<<1, 64>>>(Wq, gammaQ, betaQ, gammaK, betaK);
    attn_kernel<<<B_TOT / 8, 256>>>(command, Wq, out);
}

// round 14
// speedup vs baseline: 1.0363x; 1.0363x over previous
#include <cuda_runtime.h>
#include <cuda_fp16.h>
#include <cstdint>
#include <math.h>

#define B_TOT 65536
#define EPS 1e-5f
#define NXF (65536 * 256)          // floats per X plane
#define NWF (1024 * 256)           // floats per W plane

// ---------------- scratch (static device globals; no runtime alloc) ----------
__device__ __half g_Kh[(size_t)B_TOT * 2048];          // 256 MB (fp16 K)
__device__ __half g_Vh[(size_t)B_TOT * 2048];          // 256 MB (fp16 V)
__device__ __half g_Xh[(size_t)2 * NXF];               // 64 MB (fp16 X)
__device__ __half g_Wh[(size_t)4 * NWF];               // 2 MB (fp16 W)
__device__ float g_sumK[64];
__device__ float g_sumK2[64];
__device__ float g_cmd[20];
__device__ float g_cst[256];

// ================= PTX helpers (sm_80-era; safe on plain sm_103) =============
__device__ __forceinline__ uint32_t smem_u32(const void* p) {
    uint32_t a;
    asm("{ .reg .u64 t; cvta.to.shared.u64 t, %1; cvt.u32.u64 %0, t; }" : "=r"(a) : "l"(p));
    return a;
}
#define CP16(dst, src) \
    asm volatile("cp.async.cg.shared.global [%0], [%1], 16;" :: "r"(dst), "l"(src))
#define CP_COMMIT() asm volatile("cp.async.commit_group;")
#define CP_WAIT2()  asm volatile("cp.async.wait_group 2;")
#define CP_WAIT1()  asm volatile("cp.async.wait_group 1;")
#define CP_WAIT0()  asm volatile("cp.async.wait_group 0;")

#define LDSM4(r0, r1, r2, r3, addr) \
    asm volatile("ldmatrix.sync.aligned.m8n8.x4.shared.b16 {%0,%1,%2,%3}, [%4];" \
                 : "=r"(r0), "=r"(r1), "=r"(r2), "=r"(r3) : "r"(addr))

#define MMA16816(d, a, b0, b1) \
    asm volatile("mma.sync.aligned.m16n8k16.row.col.f32.f16.f16.f32 " \
                 "{%0,%1,%2,%3},{%4,%5,%6,%7},{%8,%9},{%0,%1,%2,%3};" \
                 : "+f"((d)[0]), "+f"((d)[1]), "+f"((d)[2]), "+f"((d)[3]) \
                 : "r"((a)[0]), "r"((a)[1]), "r"((a)[2]), "r"((a)[3]), \
                   "r"(b0), "r"(b1))

// ---------------- zero the accumulators --------------------------------------
__global__ void zero_stats_kernel() {
    int t = threadIdx.x;
    if (t < 64) { g_sumK[t] = 0.f; g_sumK2[t] = 0.f; }
    if (t < 20) { g_cmd[t] = 0.f; }
}

// ---------------- command column sums + 4x4 Gram ------------------------------
__global__ void cmd_stats_kernel(const float* __restrict__ command) {
    float s[4]  = {0.f, 0.f, 0.f, 0.f};
    float g[16] = {0.f};
    int stride = gridDim.x * blockDim.x;
    for (int b = blockIdx.x * blockDim.x + threadIdx.x; b < B_TOT; b += stride) {
        float4 c = *(const float4*)(command + (size_t)b * 4);
        float v[4] = {c.x, c.y, c.z, c.w};
        #pragma unroll
        for (int i = 0; i < 4; i++) {
            s[i] += v[i];
            #pragma unroll
            for (int j = 0; j < 4; j++) g[i * 4 + j] += v[i] * v[j];
        }
    }
    __shared__ float sh[20];
    if (threadIdx.x < 20) sh[threadIdx.x] = 0.f;
    __syncthreads();
    #pragma unroll
    for (int i = 0; i < 4; i++) atomicAdd(&sh[i], s[i]);
    #pragma unroll
    for (int i = 0; i < 16; i++) atomicAdd(&sh[4 + i], g[i]);
    __syncthreads();
    if (threadIdx.x < 20) atomicAdd(&g_cmd[threadIdx.x], sh[threadIdx.x]);
}

// ---------------- convert X and W to fp16 -------------------------------------
__global__ __launch_bounds__(256) void split_kernel(
    const float* __restrict__ f, const float* __restrict__ h,
    const float* __restrict__ wkz, const float* __restrict__ wkh,
    const float* __restrict__ wvz, const float* __restrict__ wvh)
{
    const size_t NX4 = (size_t)2 * NXF / 4;
    size_t gid = (size_t)blockIdx.x * 256 + threadIdx.x;

    const float* src;
    __half* dst;
    size_t base;
    if (gid < NX4) {
        base = gid * 4;
        src = (base < (size_t)NXF) ? (f + base) : (h + (base - NXF));
        dst = g_Xh + base;
    } else {
        base = (gid - NX4) * 4;
        size_t o = base;
        if      (o < (size_t)NWF)       src = wkz + o;
        else if (o < (size_t)2 * NWF)   src = wkh + (o - NWF);
        else if (o < (size_t)3 * NWF)   src = wvz + (o - 2 * (size_t)NWF);
        else                            src = wvh + (o - 3 * (size_t)NWF);
        dst = g_Wh + base;
    }
    float4 v = *(const float4*)src;
    float vv[4] = {v.x, v.y, v.z, v.w};
    ushort4 uh;
    unsigned short* ph = (unsigned short*)&uh;
    #pragma unroll
    for (int i = 0; i < 4; i++)
        ph[i] = __half_as_ushort(__float2half_rn(vv[i]));
    *(ushort4*)dst = uh;
}

// =============================================================================
// HMMA fp16 GEMM, B-RESIDENT, kc-unrolled (R12 proven config).
// 1024 CTAs x 512 threads (16 warps, warp tile 32x64).
//   combo = blk & 15  -> which = combo & 3, coltile = combo >> 2
//   rg    = blk >> 4  -> row blocks rg*8 .. rg*8+7 (128 rows each)
// B tile (256x256 fp16 = 128KB) resident; A streamed via 4-stage 16KB ring
// where stage == kc (all stage/swizzle addresses compile-time).
// smem: B 131072 | A 4*16384 = 196608 bytes.
// =============================================================================
#define B_RES   131072
#define ASTG    16384
#define GEMM_SMEM (B_RES + 4 * ASTG)

__global__ __launch_bounds__(512, 1) void gemm_mma_kernel()
{
    extern __shared__ char sm[];
    const uint32_t sb = smem_u32(sm);
    __shared__ float sd[64], sd2[64];

    const int tid  = threadIdx.x;
    const int warp = tid >> 5;
    const int lane = tid & 31;
    const int wm   = (warp >> 2) * 32;     // warp M origin 0..96
    const int wn   = (warp & 3) * 64;      // warp N origin 0..192

    const int blk     = blockIdx.x;
    const int combo   = blk & 15;
    const int which   = combo & 3;
    const int coltile = combo >> 2;
    const int rg      = blk >> 4;          // 0..63
    const int col0    = coltile * 256;
    const int jb      = (which & 1) * 1024;
    const int p       = which & 1;

    const __half* __restrict__ Xh = g_Xh + (size_t)p * NXF;
    const __half* __restrict__ Wc = g_Wh + (size_t)which * NWF;

    if (tid < 64) { sd[tid] = 0.f; sd2[tid] = 0.f; }

    float acc[2][8][4];
    #pragma unroll
    for (int a = 0; a < 2; a++)
        #pragma unroll
        for (int b = 0; b < 8; b++)
            #pragma unroll
            for (int c = 0; c < 4; c++) acc[a][b][c] = 0.f;

    // ---- B resident load: 256 rows x 512B; thread -> row tid>>1, 16 chunks ---
    {
        const int n   = tid >> 1;
        const int c0  = (tid & 1) * 16;
        const __half* s0 = Wc + (size_t)(col0 + n) * 256;
        const uint32_t nb = sb + n * 512;
        #pragma unroll
        for (int q = 0; q < 16; q++) {
            int ch = c0 + q;
            uint32_t sw = (uint32_t)((ch & 24) | ((ch ^ (n & 7)) & 7)) << 4;
            CP16(nb + sw, s0 + ch * 8);
        }
    }
    CP_COMMIT();   // group: B

    // ---- A chunk issue (kcL/stage compile-time at call sites) ----------------
    auto issueA = [&](int block, int kcL) {
        const int rowg  = (rg * 8 + block) * 128;
        const int r     = tid >> 2;
        const int c0    = (tid & 3) * 2;
        const __half* s0 = Xh + (size_t)(rowg + r) * 256 + kcL * 64;
        const uint32_t rb = sb + B_RES + kcL * ASTG + r * 128;
        #pragma unroll
        for (int q = 0; q < 2; q++) {
            int ch = c0 + q;
            uint32_t sw = (uint32_t)(ch ^ (r & 7)) << 4;
            CP16(rb + sw, s0 + ch * 8);
        }
    };

    issueA(0, 0); CP_COMMIT();
    issueA(0, 1); CP_COMMIT();
    issueA(0, 2); CP_COMMIT();

    const int rlo   = lane >> 2;
    const int cpair = (lane & 3) * 2;
    const int lrow  = lane & 15;
    const int lhalf = lane >> 4;

    __half* C = (which < 2) ? g_Kh : g_Vh;
    const bool dostats = (which < 2);

    for (int blkI = 0; blkI < 8; blkI++) {
        #pragma unroll
        for (int kc = 0; kc < 4; kc++) {
            const int g = blkI * 4 + kc;
            {
                int rem = 31 - g;
                if (rem >= 2)      { CP_WAIT2(); }
                else if (rem == 1) { CP_WAIT1(); }
                else               { CP_WAIT0(); }
            }
            __syncthreads();
            {
                const int kcN  = (kc + 3) & 3;
                const int blkN = blkI + (kc >= 1 ? 1 : 0);
                if (blkN < 8) { issueA(blkN, kcN); CP_COMMIT(); }
            }

            const uint32_t astg = sb + B_RES + kc * ASTG;   // literal offset

            #pragma unroll
            for (int k16 = 0; k16 < 4; k16++) {
                uint32_t ah[2][4];
                #pragma unroll
                for (int mf = 0; mf < 2; mf++) {
                    int r  = wm + mf * 16 + lrow;
                    int ch = 2 * k16 + lhalf;               // literal 2*k16
                    uint32_t ad = astg + r * 128 + ((uint32_t)(ch ^ (r & 7)) << 4);
                    LDSM4(ah[mf][0], ah[mf][1], ah[mf][2], ah[mf][3], ad);
                }
                #pragma unroll
                for (int j = 0; j < 4; j++) {
                    int n  = wn + j * 16 + lrow;
                    int ch = kc * 8 + 2 * k16 + lhalf;      // literal kc, k16
                    uint32_t sw = (uint32_t)((ch & 24) | ((ch ^ (n & 7)) & 7)) << 4;
                    uint32_t bd = sb + n * 512 + sw;
                    uint32_t b0, b1, b2, b3;
                    LDSM4(b0, b1, b2, b3, bd);
                    #pragma unroll
                    for (int mf = 0; mf < 2; mf++) {
                        MMA16816(acc[mf][2 * j],     ah[mf], b0, b2);
                        MMA16816(acc[mf][2 * j + 1], ah[mf], b1, b3);
                    }
                }
            }
        }

        // -------- block epilogue: fp16 direct store + (K combos) stats --------
        {
            const int rowg = (rg * 8 + blkI) * 128;
            #pragma unroll
            for (int mf = 0; mf < 2; mf++) {
                #pragma unroll
                for (int nf = 0; nf < 8; nf++) {
                    int row = rowg + wm + mf * 16 + rlo;
                    int col = jb + col0 + wn + nf * 8 + cpair;
                    *(__half2*)(C + (size_t)row * 2048 + col) =
                        __floats2half2_rn(acc[mf][nf][0], acc[mf][nf][1]);
                    *(__half2*)(C + (size_t)(row + 8) * 2048 + col) =
                        __floats2half2_rn(acc[mf][nf][2], acc[mf][nf][3]);
                }
            }
            if (dostats) {
                #pragma unroll
                for (int nf = 0; nf < 8; nf++) {
                    float s0 = 0.f, s1 = 0.f, q0 = 0.f, q1 = 0.f;
                    #pragma unroll
                    for (int mf = 0; mf < 2; mf++) {
                        float a0 = acc[mf][nf][0], a1 = acc[mf][nf][1];
                        float a2 = acc[mf][nf][2], a3 = acc[mf][nf][3];
                        s0 += a0 + a2;  s1 += a1 + a3;
                        q0 += a0 * a0 + a2 * a2;
                        q1 += a1 * a1 + a3 * a3;
                    }
                    #pragma unroll
                    for (int o = 4; o <= 16; o <<= 1) {
                        s0 += __shfl_xor_sync(0xffffffffu, s0, o);
                        s1 += __shfl_xor_sync(0xffffffffu, s1, o);
                        q0 += __shfl_xor_sync(0xffffffffu, q0, o);
                        q1 += __shfl_xor_sync(0xffffffffu, q1, o);
                    }
                    if (lane < 4) {
                        int d = (wn + nf * 8 + lane * 2) & 63;
                        atomicAdd(&sd[d], s0);   atomicAdd(&sd[d + 1], s1);
                        atomicAdd(&sd2[d], q0);  atomicAdd(&sd2[d + 1], q1);
                    }
                }
            }
            #pragma unroll
            for (int a = 0; a < 2; a++)
                #pragma unroll
                for (int b = 0; b < 8; b++)
                    #pragma unroll
                    for (int c2 = 0; c2 < 4; c2++) acc[a][b][c2] = 0.f;
        }
    }

    __syncthreads();
    if (dostats && tid < 64) {
        atomicAdd(&g_sumK[tid], sd[tid]);
        atomicAdd(&g_sumK2[tid], sd2[tid]);
    }
}

// ---------------- fold BN stats into per-d affine constants ------------------
__global__ void finalize_kernel(const float* __restrict__ Wq,
                                const float* __restrict__ gammaQ,
                                const float* __restrict__ betaQ,
                                const float* __restrict__ gammaK,
                                const float* __restrict__ betaK)
{
    int d = threadIdx.x;
    if (d >= 64) return;
    const float invB = 1.f / 65536.f;

    float w[4];
    #pragma unroll
    for (int c = 0; c < 4; c++) w[c] = Wq[d * 4 + c];

    float mQ = 0.f;
    #pragma unroll
    for (int c = 0; c < 4; c++) mQ += (g_cmd[c] * invB) * w[c];
    float eq2 = 0.f;
    #pragma unroll
    for (int c1 = 0; c1 < 4; c1++)
        #pragma unroll
        for (int c2 = 0; c2 < 4; c2++)
            eq2 += w[c1] * w[c2] * g_cmd[4 + c1 * 4 + c2];
    eq2 *= invB;
    float vQ = eq2 - mQ * mQ;
    float gq = gammaQ[d] / sqrtf(vQ + EPS);
    g_cst[d]      = gq;
    g_cst[64 + d] = betaQ[d] - mQ * gq;

    const float invBF = 1.f / (65536.f * 32.f);
    float mK = g_sumK[d] * invBF;
    float vK = g_sumK2[d] * invBF - mK * mK;
    float aK = gammaK[d] / sqrtf(vK + EPS);
    g_cst[128 + d] = aK;
    g_cst[192 + d] = betaK[d] - mK * aK;
}

// ---------------- attention: 1 warp per batch row, LDG.64 vectorized ----------
// lane l: group g = l>>4 (f parity), m = l&15, owns d-quad {4m..4m+3}.
// K/V load i (uint2, 8B/lane): warp covers 256B = f rows {2i, 2i+1};
// this lane gets f = 2i+g, d = 4m..4m+3.
// 15-step butterfly within 16-lane groups -> lane holds logit for f = 2m+g.
__global__ __launch_bounds__(256) void attn_kernel(
    const float* __restrict__ command, const float* __restrict__ Wq,
    float* __restrict__ out)
{
    const int w    = threadIdx.x >> 5;
    const int lane = threadIdx.x & 31;
    const int b    = blockIdx.x * 8 + w;
    const int m    = lane & 15;
    const int g16  = lane >> 4;

    float4 c4 = *(const float4*)(command + (size_t)b * 4);

    // q projection + BN fold for d-quad 4m..4m+3
    float qa[4];
    float qcp = 0.f;
    #pragma unroll
    for (int j = 0; j < 4; j++) {
        int d = 4 * m + j;
        float q = c4.x * Wq[d * 4 + 0] + c4.y * Wq[d * 4 + 1] +
                  c4.z * Wq[d * 4 + 2] + c4.w * Wq[d * 4 + 3];
        float qn = q * g_cst[d] + g_cst[64 + d];
        qa[j] = qn * g_cst[128 + d];
        qcp  += qn * g_cst[192 + d];
    }
    // qc: both g16 groups computed the same quads -> sum over 32 lanes = 2x
    #pragma unroll
    for (int o = 16; o; o >>= 1) qcp += __shfl_xor_sync(0xffffffffu, qcp, o);
    const float qc = qcp * 0.5f;

    // K partials: 16 x LDG.64, each lane: f = 2i+g16, d-quad m
    const uint2* Kr = (const uint2*)(g_Kh + (size_t)b * 2048) + lane;
    float p[16];
    #pragma unroll
    for (int i = 0; i < 16; i++) {
        uint2 kv = Kr[i * 32];
        float2 k01 = __half22float2(*(__half2*)&kv.x);
        float2 k23 = __half22float2(*(__half2*)&kv.y);
        p[i] = qa[0] * k01.x + qa[1] * k01.y + qa[2] * k23.x + qa[3] * k23.y;
    }

    // butterfly transpose-reduce within 16-lane group: lane m -> logit f=2m+g16
    #pragma unroll
    for (int o = 8; o >= 1; o >>= 1) {
        #pragma unroll
        for (int j = 0; j < o; j++) {
            bool hi = (m & o) != 0;
            float keep = hi ? p[j + o] : p[j];
            float send = hi ? p[j] : p[j + o];
            p[j] = keep + __shfl_xor_sync(0xffffffffu, send, o);
        }
    }
    float logit = (p[0] + qc) * 0.125f;   // this lane: f = 2m + g16

    // softmax over all 32 lanes (every f represented exactly once)
    float mx = logit;
    #pragma unroll
    for (int o = 16; o; o >>= 1) mx = fmaxf(mx, __shfl_xor_sync(0xffffffffu, mx, o));
    float e = __expf(logit - mx);
    float den = e;
    #pragma unroll
    for (int o = 16; o; o >>= 1) den += __shfl_xor_sync(0xffffffffu, den, o);
    float a = e / den;

    // V pass: same load mapping; af for f = 2i+g16 lives on lane (g16<<4)|i
    const uint2* Vr = (const uint2*)(g_Vh + (size_t)b * 2048) + lane;
    float s0 = 0.f, s1 = 0.f, s2 = 0.f, s3 = 0.f;
    const int srcbase = g16 << 4;
    #pragma unroll
    for (int i = 0; i < 16; i++) {
        float af = __shfl_sync(0xffffffffu, a, srcbase | i);
        uint2 vv = Vr[i * 32];
        float2 v01 = __half22float2(*(__half2*)&vv.x);
        float2 v23 = __half22float2(*(__half2*)&vv.y);
        s0 += af * v01.x;  s1 += af * v01.y;
        s2 += af * v23.x;  s3 += af * v23.y;
    }
    // merge the two f-parity halves (partner lane has same d-quad)
    s0 += __shfl_xor_sync(0xffffffffu, s0, 16);
    s1 += __shfl_xor_sync(0xffffffffu, s1, 16);
    s2 += __shfl_xor_sync(0xffffffffu, s2, 16);
    s3 += __shfl_xor_sync(0xffffffffu, s3, 16);

    // write: g16=0 lanes store d {4m,4m+1}, g16=1 lanes store d {4m+2,4m+3}
    float2 o2 = (g16 == 0) ? make_float2(s0, s1) : make_float2(s2, s3);
    *(float2*)(out + (size_t)b * 64 + 4 * m + 2 * g16) = o2;
}

// ---------------- launch ------------------------------------------------------
extern "C" void kernel_launch(void* const* d_in, const int* in_sizes, int n_in,
                              void* d_out, int out_size)
{
    const float* feature = (const float*)d_in[0];
    const float* hidden  = (const float*)d_in[1];
    const float* command = (const float*)d_in[2];
    const float* Wq      = (const float*)d_in[3];
    const float* Wkz     = (const float*)d_in[4];
    const float* Wkh     = (const float*)d_in[5];
    const float* Wvz     = (const float*)d_in[6];
    const float* Wvh     = (const float*)d_in[7];
    const float* gammaQ  = (const float*)d_in[8];
    const float* betaQ   = (const float*)d_in[9];
    const float* gammaK  = (const float*)d_in[10];
    const float* betaK   = (const float*)d_in[11];
    float* out = (float*)d_out;

    cudaFuncSetAttribute(gemm_mma_kernel,
                         cudaFuncAttributeMaxDynamicSharedMemorySize, GEMM_SMEM);

    zero_stats_kernel<<<1, 64>>>();
    cmd_stats_kernel<<<128, 256>>>(command);
    split_kernel<<<33792, 256>>>(feature, hidden, Wkz, Wkh, Wvz, Wvh);
    gemm_mma_kernel<<<1024, 512, GEMM_SMEM>>>();
    finalize_kernel<<<1, 64>>>(Wq, gammaQ, betaQ, gammaK, betaK);
    attn_kernel<<<B_TOT / 8, 256>>>(command, Wq, out);
}

// round 16
// speedup vs baseline: 1.0643x; 1.0270x over previous
#include <cuda_runtime.h>
#include <cuda_fp16.h>
#include <cstdint>
#include <math.h>

#define B_TOT 65536
#define EPS 1e-5f
#define NXF (65536 * 256)          // floats per X plane
#define NWF (1024 * 256)           // floats per W plane

// ---------------- scratch (static device globals; no runtime alloc) ----------
__device__ __half g_Kh[(size_t)B_TOT * 2048];          // 256 MB (fp16 K)
__device__ __half g_Vh[(size_t)B_TOT * 2048];          // 256 MB (fp16 V)
__device__ __half g_Xh[(size_t)2 * NXF];               // 64 MB (fp16 X)
__device__ __half g_Wh[(size_t)4 * NWF];               // 2 MB (fp16 W)
__device__ float g_sumK[64];
__device__ float g_sumK2[64];
__device__ float g_cmd[20];
__device__ float g_cst[256];

// ================= PTX helpers (sm_80-era; safe on plain sm_103) =============
__device__ __forceinline__ uint32_t smem_u32(const void* p) {
    uint32_t a;
    asm("{ .reg .u64 t; cvta.to.shared.u64 t, %1; cvt.u32.u64 %0, t; }" : "=r"(a) : "l"(p));
    return a;
}
#define CP16(dst, src) \
    asm volatile("cp.async.cg.shared.global [%0], [%1], 16;" :: "r"(dst), "l"(src))
#define CP_COMMIT() asm volatile("cp.async.commit_group;")
#define CP_WAIT0()  asm volatile("cp.async.wait_group 0;")

#define LDSM4(r0, r1, r2, r3, addr) \
    asm volatile("ldmatrix.sync.aligned.m8n8.x4.shared.b16 {%0,%1,%2,%3}, [%4];" \
                 : "=r"(r0), "=r"(r1), "=r"(r2), "=r"(r3) : "r"(addr))

#define MMA16816(d, a, b0, b1) \
    asm volatile("mma.sync.aligned.m16n8k16.row.col.f32.f16.f16.f32 " \
                 "{%0,%1,%2,%3},{%4,%5,%6,%7},{%8,%9},{%0,%1,%2,%3};" \
                 : "+f"((d)[0]), "+f"((d)[1]), "+f"((d)[2]), "+f"((d)[3]) \
                 : "r"((a)[0]), "r"((a)[1]), "r"((a)[2]), "r"((a)[3]), \
                   "r"(b0), "r"(b1))

// ---------------- zero the accumulators --------------------------------------
__global__ void zero_stats_kernel() {
    int t = threadIdx.x;
    if (t < 64) { g_sumK[t] = 0.f; g_sumK2[t] = 0.f; }
    if (t < 20) { g_cmd[t] = 0.f; }
}

// ---------------- command column sums + 4x4 Gram ------------------------------
__global__ void cmd_stats_kernel(const float* __restrict__ command) {
    float s[4]  = {0.f, 0.f, 0.f, 0.f};
    float g[16] = {0.f};
    int stride = gridDim.x * blockDim.x;
    for (int b = blockIdx.x * blockDim.x + threadIdx.x; b < B_TOT; b += stride) {
        float4 c = *(const float4*)(command + (size_t)b * 4);
        float v[4] = {c.x, c.y, c.z, c.w};
        #pragma unroll
        for (int i = 0; i < 4; i++) {
            s[i] += v[i];
            #pragma unroll
            for (int j = 0; j < 4; j++) g[i * 4 + j] += v[i] * v[j];
        }
    }
    __shared__ float sh[20];
    if (threadIdx.x < 20) sh[threadIdx.x] = 0.f;
    __syncthreads();
    #pragma unroll
    for (int i = 0; i < 4; i++) atomicAdd(&sh[i], s[i]);
    #pragma unroll
    for (int i = 0; i < 16; i++) atomicAdd(&sh[4 + i], g[i]);
    __syncthreads();
    if (threadIdx.x < 20) atomicAdd(&g_cmd[threadIdx.x], sh[threadIdx.x]);
}

// ---------------- convert X and W to fp16 -------------------------------------
__global__ __launch_bounds__(256) void split_kernel(
    const float* __restrict__ f, const float* __restrict__ h,
    const float* __restrict__ wkz, const float* __restrict__ wkh,
    const float* __restrict__ wvz, const float* __restrict__ wvh)
{
    const size_t NX4 = (size_t)2 * NXF / 4;
    size_t gid = (size_t)blockIdx.x * 256 + threadIdx.x;

    const float* src;
    __half* dst;
    size_t base;
    if (gid < NX4) {
        base = gid * 4;
        src = (base < (size_t)NXF) ? (f + base) : (h + (base - NXF));
        dst = g_Xh + base;
    } else {
        base = (gid - NX4) * 4;
        size_t o = base;
        if      (o < (size_t)NWF)       src = wkz + o;
        else if (o < (size_t)2 * NWF)   src = wkh + (o - NWF);
        else if (o < (size_t)3 * NWF)   src = wvz + (o - 2 * (size_t)NWF);
        else                            src = wvh + (o - 3 * (size_t)NWF);
        dst = g_Wh + base;
    }
    float4 v = *(const float4*)src;
    float vv[4] = {v.x, v.y, v.z, v.w};
    ushort4 uh;
    unsigned short* ph = (unsigned short*)&uh;
    #pragma unroll
    for (int i = 0; i < 4; i++)
        ph[i] = __half_as_ushort(__float2half_rn(vv[i]));
    *(ushort4*)dst = uh;
}

// =============================================================================
// HMMA fp16 GEMM, B-RESIDENT, kc-unrolled, PAIRED pipeline (16 barriers).
// 1024 CTAs x 512 threads (16 warps, warp tile 32x64).
//   combo = blk & 15  -> which = combo & 3, coltile = combo >> 2
//   rg    = blk >> 4  -> row blocks rg*8 .. rg*8+7 (128 rows each)
// B tile (256x256 fp16 = 128KB) resident; A streamed via 4-stage 16KB ring,
// stage == kc (compile-time). Chunks processed in PAIRS: WAIT0 retires the
// current pair (only pair outstanding), one barrier, then issue the next pair
// into the two stages whose readers finished before this barrier.
// smem: B 131072 | A 4*16384 = 196608 bytes.
// =============================================================================
#define B_RES   131072
#define ASTG    16384
#define GEMM_SMEM (B_RES + 4 * ASTG)

__global__ __launch_bounds__(512, 1) void gemm_mma_kernel()
{
    extern __shared__ char sm[];
    const uint32_t sb = smem_u32(sm);
    __shared__ float sd[64], sd2[64];

    const int tid  = threadIdx.x;
    const int warp = tid >> 5;
    const int lane = tid & 31;
    const int wm   = (warp >> 2) * 32;     // warp M origin 0..96
    const int wn   = (warp & 3) * 64;      // warp N origin 0..192

    const int blk     = blockIdx.x;
    const int combo   = blk & 15;
    const int which   = combo & 3;
    const int coltile = combo >> 2;
    const int rg      = blk >> 4;          // 0..63
    const int col0    = coltile * 256;
    const int jb      = (which & 1) * 1024;
    const int p       = which & 1;

    const __half* __restrict__ Xh = g_Xh + (size_t)p * NXF;
    const __half* __restrict__ Wc = g_Wh + (size_t)which * NWF;

    if (tid < 64) { sd[tid] = 0.f; sd2[tid] = 0.f; }

    float acc[2][8][4];
    #pragma unroll
    for (int a = 0; a < 2; a++)
        #pragma unroll
        for (int b = 0; b < 8; b++)
            #pragma unroll
            for (int c = 0; c < 4; c++) acc[a][b][c] = 0.f;

    // ---- B resident load: 256 rows x 512B; thread -> row tid>>1, 16 chunks ---
    {
        const int n   = tid >> 1;
        const int c0  = (tid & 1) * 16;
        const __half* s0 = Wc + (size_t)(col0 + n) * 256;
        const uint32_t nb = sb + n * 512;
        #pragma unroll
        for (int q = 0; q < 16; q++) {
            int ch = c0 + q;
            uint32_t sw = (uint32_t)((ch & 24) | ((ch ^ (n & 7)) & 7)) << 4;
            CP16(nb + sw, s0 + ch * 8);
        }
    }
    CP_COMMIT();   // group: B

    // ---- A chunk issue (kcL/stage compile-time at call sites) ----------------
    auto issueA = [&](int block, int kcL) {
        const int rowg  = (rg * 8 + block) * 128;
        const int r     = tid >> 2;
        const int c0    = (tid & 3) * 2;
        const __half* s0 = Xh + (size_t)(rowg + r) * 256 + kcL * 64;
        const uint32_t rb = sb + B_RES + kcL * ASTG + r * 128;
        #pragma unroll
        for (int q = 0; q < 2; q++) {
            int ch = c0 + q;
            uint32_t sw = (uint32_t)(ch ^ (r & 7)) << 4;
            CP16(rb + sw, s0 + ch * 8);
        }
    };

    // prologue: first pair (chunks 0,1 of block 0) as one group
    issueA(0, 0);
    issueA(0, 1);
    CP_COMMIT();

    const int rlo   = lane >> 2;
    const int cpair = (lane & 3) * 2;
    const int lrow  = lane & 15;
    const int lhalf = lane >> 4;

    __half* C = (which < 2) ? g_Kh : g_Vh;
    const bool dostats = (which < 2);

    for (int blkI = 0; blkI < 8; blkI++) {
        #pragma unroll
        for (int kp = 0; kp < 2; kp++) {   // pair: chunks kc = 2kp, 2kp+1
            CP_WAIT0();                    // only current pair (+B at start) outstanding
            __syncthreads();

            // issue next pair into the two stages freed before this barrier
            if (kp == 0) {
                issueA(blkI, 2);
                issueA(blkI, 3);
                CP_COMMIT();
            } else if (blkI + 1 < 8) {
                issueA(blkI + 1, 0);
                issueA(blkI + 1, 1);
                CP_COMMIT();
            }

            #pragma unroll
            for (int kh = 0; kh < 2; kh++) {
                const int kc = 2 * kp + kh;                 // literal
                const uint32_t astg = sb + B_RES + kc * ASTG;

                #pragma unroll
                for (int k16 = 0; k16 < 4; k16++) {
                    uint32_t ah[2][4];
                    #pragma unroll
                    for (int mf = 0; mf < 2; mf++) {
                        int r  = wm + mf * 16 + lrow;
                        int ch = 2 * k16 + lhalf;           // literal
                        uint32_t ad = astg + r * 128 +
                                      ((uint32_t)(ch ^ (r & 7)) << 4);
                        LDSM4(ah[mf][0], ah[mf][1], ah[mf][2], ah[mf][3], ad);
                    }
                    #pragma unroll
                    for (int j = 0; j < 4; j++) {
                        int n  = wn + j * 16 + lrow;
                        int ch = kc * 8 + 2 * k16 + lhalf;  // literal
                        uint32_t sw = (uint32_t)((ch & 24) |
                                                 ((ch ^ (n & 7)) & 7)) << 4;
                        uint32_t bd = sb + n * 512 + sw;
                        uint32_t b0, b1, b2, b3;
                        LDSM4(b0, b1, b2, b3, bd);
                        #pragma unroll
                        for (int mf = 0; mf < 2; mf++) {
                            MMA16816(acc[mf][2 * j],     ah[mf], b0, b2);
                            MMA16816(acc[mf][2 * j + 1], ah[mf], b1, b3);
                        }
                    }
                }
            }
        }

        // -------- block epilogue: fp16 direct store + (K combos) stats --------
        {
            const int rowg = (rg * 8 + blkI) * 128;
            #pragma unroll
            for (int mf = 0; mf < 2; mf++) {
                #pragma unroll
                for (int nf = 0; nf < 8; nf++) {
                    int row = rowg + wm + mf * 16 + rlo;
                    int col = jb + col0 + wn + nf * 8 + cpair;
                    *(__half2*)(C + (size_t)row * 2048 + col) =
                        __floats2half2_rn(acc[mf][nf][0], acc[mf][nf][1]);
                    *(__half2*)(C + (size_t)(row + 8) * 2048 + col) =
                        __floats2half2_rn(acc[mf][nf][2], acc[mf][nf][3]);
                }
            }
            if (dostats) {
                #pragma unroll
                for (int nf = 0; nf < 8; nf++) {
                    float s0 = 0.f, s1 = 0.f, q0 = 0.f, q1 = 0.f;
                    #pragma unroll
                    for (int mf = 0; mf < 2; mf++) {
                        float a0 = acc[mf][nf][0], a1 = acc[mf][nf][1];
                        float a2 = acc[mf][nf][2], a3 = acc[mf][nf][3];
                        s0 += a0 + a2;  s1 += a1 + a3;
                        q0 += a0 * a0 + a2 * a2;
                        q1 += a1 * a1 + a3 * a3;
                    }
                    #pragma unroll
                    for (int o = 4; o <= 16; o <<= 1) {
                        s0 += __shfl_xor_sync(0xffffffffu, s0, o);
                        s1 += __shfl_xor_sync(0xffffffffu, s1, o);
                        q0 += __shfl_xor_sync(0xffffffffu, q0, o);
                        q1 += __shfl_xor_sync(0xffffffffu, q1, o);
                    }
                    if (lane < 4) {
                        int d = (wn + nf * 8 + lane * 2) & 63;
                        atomicAdd(&sd[d], s0);   atomicAdd(&sd[d + 1], s1);
                        atomicAdd(&sd2[d], q0);  atomicAdd(&sd2[d + 1], q1);
                    }
                }
            }
            #pragma unroll
            for (int a = 0; a < 2; a++)
                #pragma unroll
                for (int b = 0; b < 8; b++)
                    #pragma unroll
                    for (int c2 = 0; c2 < 4; c2++) acc[a][b][c2] = 0.f;
        }
    }

    __syncthreads();
    if (dostats && tid < 64) {
        atomicAdd(&g_sumK[tid], sd[tid]);
        atomicAdd(&g_sumK2[tid], sd2[tid]);
    }
}

// ---------------- fold BN stats into per-d affine constants ------------------
__global__ void finalize_kernel(const float* __restrict__ Wq,
                                const float* __restrict__ gammaQ,
                                const float* __restrict__ betaQ,
                                const float* __restrict__ gammaK,
                                const float* __restrict__ betaK)
{
    int d = threadIdx.x;
    if (d >= 64) return;
    const float invB = 1.f / 65536.f;

    float w[4];
    #pragma unroll
    for (int c = 0; c < 4; c++) w[c] = Wq[d * 4 + c];

    float mQ = 0.f;
    #pragma unroll
    for (int c = 0; c < 4; c++) mQ += (g_cmd[c] * invB) * w[c];
    float eq2 = 0.f;
    #pragma unroll
    for (int c1 = 0; c1 < 4; c1++)
        #pragma unroll
        for (int c2 = 0; c2 < 4; c2++)
            eq2 += w[c1] * w[c2] * g_cmd[4 + c1 * 4 + c2];
    eq2 *= invB;
    float vQ = eq2 - mQ * mQ;
    float gq = gammaQ[d] / sqrtf(vQ + EPS);
    g_cst[d]      = gq;
    g_cst[64 + d] = betaQ[d] - mQ * gq;

    const float invBF = 1.f / (65536.f * 32.f);
    float mK = g_sumK[d] * invBF;
    float vK = g_sumK2[d] * invBF - mK * mK;
    float aK = gammaK[d] / sqrtf(vK + EPS);
    g_cst[128 + d] = aK;
    g_cst[192 + d] = betaK[d] - mK * aK;
}

// ---------------- attention: 1 warp per batch row, coalesced K (R12 ver) ------
__global__ __launch_bounds__(256) void attn_kernel(
    const float* __restrict__ command, const float* __restrict__ Wq,
    float* __restrict__ out)
{
    const int w    = threadIdx.x >> 5;
    const int lane = threadIdx.x & 31;
    const int b    = blockIdx.x * 8 + w;

    float4 c4 = *(const float4*)(command + (size_t)b * 4);
    const int d0 = 2 * lane, d1 = 2 * lane + 1;

    float q0 = c4.x * Wq[d0 * 4 + 0] + c4.y * Wq[d0 * 4 + 1] +
               c4.z * Wq[d0 * 4 + 2] + c4.w * Wq[d0 * 4 + 3];
    float q1 = c4.x * Wq[d1 * 4 + 0] + c4.y * Wq[d1 * 4 + 1] +
               c4.z * Wq[d1 * 4 + 2] + c4.w * Wq[d1 * 4 + 3];
    float qn0 = q0 * g_cst[d0] + g_cst[64 + d0];
    float qn1 = q1 * g_cst[d1] + g_cst[64 + d1];

    float qa0 = qn0 * g_cst[128 + d0];
    float qa1 = qn1 * g_cst[128 + d1];
    float qc  = qn0 * g_cst[192 + d0] + qn1 * g_cst[192 + d1];
    #pragma unroll
    for (int o = 16; o; o >>= 1) qc += __shfl_xor_sync(0xffffffffu, qc, o);

    // per-f partials over this lane's d-pair (coalesced 128B per f)
    const __half2* Kr = (const __half2*)(g_Kh + (size_t)b * 2048) + lane;
    float p[32];
    #pragma unroll
    for (int f = 0; f < 32; f++) {
        float2 kf = __half22float2(Kr[f * 32]);
        p[f] = qa0 * kf.x + qa1 * kf.y;
    }

    // butterfly transpose-reduce: lane l ends with full logit for f = l
    #pragma unroll
    for (int o = 16; o >= 1; o >>= 1) {
        #pragma unroll
        for (int j = 0; j < o; j++) {
            bool hi = (lane & o) != 0;
            float keep = hi ? p[j + o] : p[j];
            float send = hi ? p[j] : p[j + o];
            p[j] = keep + __shfl_xor_sync(0xffffffffu, send, o);
        }
    }
    float logit = (p[0] + qc) * 0.125f;   // 1/sqrt(64)

    float mx = logit;
    #pragma unroll
    for (int o = 16; o; o >>= 1) mx = fmaxf(mx, __shfl_xor_sync(0xffffffffu, mx, o));
    float e = __expf(logit - mx);
    float den = e;
    #pragma unroll
    for (int o = 16; o; o >>= 1) den += __shfl_xor_sync(0xffffffffu, den, o);
    float a = e / den;

    const __half2* Vr = (const __half2*)(g_Vh + (size_t)b * 2048);
    float s0 = 0.f, s1 = 0.f;
    #pragma unroll
    for (int f = 0; f < 32; f++) {
        float af = __shfl_sync(0xffffffffu, a, f);
        float2 vf = __half22float2(Vr[f * 32 + lane]);
        s0 += af * vf.x;
        s1 += af * vf.y;
    }
    *(float2*)(out + (size_t)b * 64 + 2 * lane) = make_float2(s0, s1);
}

// ---------------- launch ------------------------------------------------------
extern "C" void kernel_launch(void* const* d_in, const int* in_sizes, int n_in,
                              void* d_out, int out_size)
{
    const float* feature = (const float*)d_in[0];
    const float* hidden  = (const float*)d_in[1];
    const float* command = (const float*)d_in[2];
    const float* Wq      = (const float*)d_in[3];
    const float* Wkz     = (const float*)d_in[4];
    const float* Wkh     = (const float*)d_in[5];
    const float* Wvz     = (const float*)d_in[6];
    const float* Wvh     = (const float*)d_in[7];
    const float* gammaQ  = (const float*)d_in[8];
    const float* betaQ   = (const float*)d_in[9];
    const float* gammaK  = (const float*)d_in[10];
    const float* betaK   = (const float*)d_in[11];
    float* out = (float*)d_out;

    cudaFuncSetAttribute(gemm_mma_kernel,
                         cudaFuncAttributeMaxDynamicSharedMemorySize, GEMM_SMEM);

    zero_stats_kernel<<<1, 64>>>();
    cmd_stats_kernel<<<128, 256>>>(command);
    split_kernel<<<33792, 256>>>(feature, hidden, Wkz, Wkh, Wvz, Wvh);
    gemm_mma_kernel<<<1024, 512, GEMM_SMEM>>>();
    finalize_kernel<<<1, 64>>>(Wq, gammaQ, betaQ, gammaK, betaK);
    attn_kernel<<<B_TOT / 8, 256>>>(command, Wq, out);
}

// round 17
// speedup vs baseline: 1.0680x; 1.0035x over previous
#include <cuda_runtime.h>
#include <cuda_fp16.h>
#include <cstdint>
#include <math.h>

#define B_TOT 65536
#define EPS 1e-5f
#define NXF (65536 * 256)          // floats per X plane
#define NWF (1024 * 256)           // floats per W plane

// ---------------- scratch (static device globals; no runtime alloc) ----------
__device__ __half g_Kh[(size_t)B_TOT * 2048];          // 256 MB (fp16 K)
__device__ __half g_Vh[(size_t)B_TOT * 2048];          // 256 MB (fp16 V)
__device__ __half g_Xh[(size_t)2 * NXF];               // 64 MB (fp16 X)
__device__ __half g_Wh[(size_t)4 * NWF];               // 2 MB (fp16 W)
__device__ float g_sumK[64];
__device__ float g_sumK2[64];
__device__ float g_cmd[20];
__device__ float g_cst[256];

// ================= PTX helpers (sm_80-era; safe on plain sm_103) =============
__device__ __forceinline__ uint32_t smem_u32(const void* p) {
    uint32_t a;
    asm("{ .reg .u64 t; cvta.to.shared.u64 t, %1; cvt.u32.u64 %0, t; }" : "=r"(a) : "l"(p));
    return a;
}
#define CP16(dst, src) \
    asm volatile("cp.async.cg.shared.global [%0], [%1], 16;" :: "r"(dst), "l"(src))
#define CP_COMMIT() asm volatile("cp.async.commit_group;")
#define CP_WAIT0()  asm volatile("cp.async.wait_group 0;")

#define LDSM4(r0, r1, r2, r3, addr) \
    asm volatile("ldmatrix.sync.aligned.m8n8.x4.shared.b16 {%0,%1,%2,%3}, [%4];" \
                 : "=r"(r0), "=r"(r1), "=r"(r2), "=r"(r3) : "r"(addr))

#define MMA16816(d, a, b0, b1) \
    asm volatile("mma.sync.aligned.m16n8k16.row.col.f32.f16.f16.f32 " \
                 "{%0,%1,%2,%3},{%4,%5,%6,%7},{%8,%9},{%0,%1,%2,%3};" \
                 : "+f"((d)[0]), "+f"((d)[1]), "+f"((d)[2]), "+f"((d)[3]) \
                 : "r"((a)[0]), "r"((a)[1]), "r"((a)[2]), "r"((a)[3]), \
                   "r"(b0), "r"(b1))

// ---------------- command column sums + 4x4 Gram ------------------------------
__global__ void cmd_stats_kernel(const float* __restrict__ command) {
    float s[4]  = {0.f, 0.f, 0.f, 0.f};
    float g[16] = {0.f};
    int stride = gridDim.x * blockDim.x;
    for (int b = blockIdx.x * blockDim.x + threadIdx.x; b < B_TOT; b += stride) {
        float4 c = *(const float4*)(command + (size_t)b * 4);
        float v[4] = {c.x, c.y, c.z, c.w};
        #pragma unroll
        for (int i = 0; i < 4; i++) {
            s[i] += v[i];
            #pragma unroll
            for (int j = 0; j < 4; j++) g[i * 4 + j] += v[i] * v[j];
        }
    }
    __shared__ float sh[20];
    if (threadIdx.x < 20) sh[threadIdx.x] = 0.f;
    __syncthreads();
    #pragma unroll
    for (int i = 0; i < 4; i++) atomicAdd(&sh[i], s[i]);
    #pragma unroll
    for (int i = 0; i < 16; i++) atomicAdd(&sh[4 + i], g[i]);
    __syncthreads();
    if (threadIdx.x < 20) atomicAdd(&g_cmd[threadIdx.x], sh[threadIdx.x]);
}

// ---------------- convert X and W to fp16 (+ block 0 zeroes stats) ------------
__global__ __launch_bounds__(256) void split_kernel(
    const float* __restrict__ f, const float* __restrict__ h,
    const float* __restrict__ wkz, const float* __restrict__ wkh,
    const float* __restrict__ wvz, const float* __restrict__ wvh)
{
    if (blockIdx.x == 0) {
        int t = threadIdx.x;
        if (t < 64) { g_sumK[t] = 0.f; g_sumK2[t] = 0.f; }
        if (t < 20) { g_cmd[t] = 0.f; }
    }

    const size_t NX4 = (size_t)2 * NXF / 4;
    size_t gid = (size_t)blockIdx.x * 256 + threadIdx.x;

    const float* src;
    __half* dst;
    size_t base;
    if (gid < NX4) {
        base = gid * 4;
        src = (base < (size_t)NXF) ? (f + base) : (h + (base - NXF));
        dst = g_Xh + base;
    } else {
        base = (gid - NX4) * 4;
        size_t o = base;
        if      (o < (size_t)NWF)       src = wkz + o;
        else if (o < (size_t)2 * NWF)   src = wkh + (o - NWF);
        else if (o < (size_t)3 * NWF)   src = wvz + (o - 2 * (size_t)NWF);
        else                            src = wvh + (o - 3 * (size_t)NWF);
        dst = g_Wh + base;
    }
    float4 v = *(const float4*)src;
    float vv[4] = {v.x, v.y, v.z, v.w};
    ushort4 uh;
    unsigned short* ph = (unsigned short*)&uh;
    #pragma unroll
    for (int i = 0; i < 4; i++)
        ph[i] = __half_as_ushort(__float2half_rn(vv[i]));
    *(ushort4*)dst = uh;
}

// =============================================================================
// HMMA fp16 GEMM, B-RESIDENT, kc-unrolled, PAIRED pipeline (R16 proven).
// 1024 CTAs x 512 threads (16 warps, warp tile 32x64).
// smem: B 131072 | A 4*16384 = 196608 bytes.
// =============================================================================
#define B_RES   131072
#define ASTG    16384
#define GEMM_SMEM (B_RES + 4 * ASTG)

__global__ __launch_bounds__(512, 1) void gemm_mma_kernel()
{
    extern __shared__ char sm[];
    const uint32_t sb = smem_u32(sm);
    __shared__ float sd[64], sd2[64];

    const int tid  = threadIdx.x;
    const int warp = tid >> 5;
    const int lane = tid & 31;
    const int wm   = (warp >> 2) * 32;     // warp M origin 0..96
    const int wn   = (warp & 3) * 64;      // warp N origin 0..192

    const int blk     = blockIdx.x;
    const int combo   = blk & 15;
    const int which   = combo & 3;
    const int coltile = combo >> 2;
    const int rg      = blk >> 4;          // 0..63
    const int col0    = coltile * 256;
    const int jb      = (which & 1) * 1024;
    const int p       = which & 1;

    const __half* __restrict__ Xh = g_Xh + (size_t)p * NXF;
    const __half* __restrict__ Wc = g_Wh + (size_t)which * NWF;

    if (tid < 64) { sd[tid] = 0.f; sd2[tid] = 0.f; }

    float acc[2][8][4];
    #pragma unroll
    for (int a = 0; a < 2; a++)
        #pragma unroll
        for (int b = 0; b < 8; b++)
            #pragma unroll
            for (int c = 0; c < 4; c++) acc[a][b][c] = 0.f;

    // ---- B resident load: 256 rows x 512B; thread -> row tid>>1, 16 chunks ---
    {
        const int n   = tid >> 1;
        const int c0  = (tid & 1) * 16;
        const __half* s0 = Wc + (size_t)(col0 + n) * 256;
        const uint32_t nb = sb + n * 512;
        #pragma unroll
        for (int q = 0; q < 16; q++) {
            int ch = c0 + q;
            uint32_t sw = (uint32_t)((ch & 24) | ((ch ^ (n & 7)) & 7)) << 4;
            CP16(nb + sw, s0 + ch * 8);
        }
    }
    CP_COMMIT();   // group: B

    // ---- A chunk issue (kcL/stage compile-time at call sites) ----------------
    auto issueA = [&](int block, int kcL) {
        const int rowg  = (rg * 8 + block) * 128;
        const int r     = tid >> 2;
        const int c0    = (tid & 3) * 2;
        const __half* s0 = Xh + (size_t)(rowg + r) * 256 + kcL * 64;
        const uint32_t rb = sb + B_RES + kcL * ASTG + r * 128;
        #pragma unroll
        for (int q = 0; q < 2; q++) {
            int ch = c0 + q;
            uint32_t sw = (uint32_t)(ch ^ (r & 7)) << 4;
            CP16(rb + sw, s0 + ch * 8);
        }
    };

    // prologue: first pair (chunks 0,1 of block 0) as one group
    issueA(0, 0);
    issueA(0, 1);
    CP_COMMIT();

    const int rlo   = lane >> 2;
    const int cpair = (lane & 3) * 2;
    const int lrow  = lane & 15;
    const int lhalf = lane >> 4;

    __half* C = (which < 2) ? g_Kh : g_Vh;
    const bool dostats = (which < 2);

    for (int blkI = 0; blkI < 8; blkI++) {
        #pragma unroll
        for (int kp = 0; kp < 2; kp++) {   // pair: chunks kc = 2kp, 2kp+1
            CP_WAIT0();
            __syncthreads();

            if (kp == 0) {
                issueA(blkI, 2);
                issueA(blkI, 3);
                CP_COMMIT();
            } else if (blkI + 1 < 8) {
                issueA(blkI + 1, 0);
                issueA(blkI + 1, 1);
                CP_COMMIT();
            }

            #pragma unroll
            for (int kh = 0; kh < 2; kh++) {
                const int kc = 2 * kp + kh;                 // literal
                const uint32_t astg = sb + B_RES + kc * ASTG;

                #pragma unroll
                for (int k16 = 0; k16 < 4; k16++) {
                    uint32_t ah[2][4];
                    #pragma unroll
                    for (int mf = 0; mf < 2; mf++) {
                        int r  = wm + mf * 16 + lrow;
                        int ch = 2 * k16 + lhalf;           // literal
                        uint32_t ad = astg + r * 128 +
                                      ((uint32_t)(ch ^ (r & 7)) << 4);
                        LDSM4(ah[mf][0], ah[mf][1], ah[mf][2], ah[mf][3], ad);
                    }
                    #pragma unroll
                    for (int j = 0; j < 4; j++) {
                        int n  = wn + j * 16 + lrow;
                        int ch = kc * 8 + 2 * k16 + lhalf;  // literal
                        uint32_t sw = (uint32_t)((ch & 24) |
                                                 ((ch ^ (n & 7)) & 7)) << 4;
                        uint32_t bd = sb + n * 512 + sw;
                        uint32_t b0, b1, b2, b3;
                        LDSM4(b0, b1, b2, b3, bd);
                        #pragma unroll
                        for (int mf = 0; mf < 2; mf++) {
                            MMA16816(acc[mf][2 * j],     ah[mf], b0, b2);
                            MMA16816(acc[mf][2 * j + 1], ah[mf], b1, b3);
                        }
                    }
                }
            }
        }

        // -------- block epilogue: fp16 direct store + (K combos) stats --------
        {
            const int rowg = (rg * 8 + blkI) * 128;
            #pragma unroll
            for (int mf = 0; mf < 2; mf++) {
                #pragma unroll
                for (int nf = 0; nf < 8; nf++) {
                    int row = rowg + wm + mf * 16 + rlo;
                    int col = jb + col0 + wn + nf * 8 + cpair;
                    *(__half2*)(C + (size_t)row * 2048 + col) =
                        __floats2half2_rn(acc[mf][nf][0], acc[mf][nf][1]);
                    *(__half2*)(C + (size_t)(row + 8) * 2048 + col) =
                        __floats2half2_rn(acc[mf][nf][2], acc[mf][nf][3]);
                }
            }
            if (dostats) {
                #pragma unroll
                for (int nf = 0; nf < 8; nf++) {
                    float s0 = 0.f, s1 = 0.f, q0 = 0.f, q1 = 0.f;
                    #pragma unroll
                    for (int mf = 0; mf < 2; mf++) {
                        float a0 = acc[mf][nf][0], a1 = acc[mf][nf][1];
                        float a2 = acc[mf][nf][2], a3 = acc[mf][nf][3];
                        s0 += a0 + a2;  s1 += a1 + a3;
                        q0 += a0 * a0 + a2 * a2;
                        q1 += a1 * a1 + a3 * a3;
                    }
                    #pragma unroll
                    for (int o = 4; o <= 16; o <<= 1) {
                        s0 += __shfl_xor_sync(0xffffffffu, s0, o);
                        s1 += __shfl_xor_sync(0xffffffffu, s1, o);
                        q0 += __shfl_xor_sync(0xffffffffu, q0, o);
                        q1 += __shfl_xor_sync(0xffffffffu, q1, o);
                    }
                    if (lane < 4) {
                        int d = (wn + nf * 8 + lane * 2) & 63;
                        atomicAdd(&sd[d], s0);   atomicAdd(&sd[d + 1], s1);
                        atomicAdd(&sd2[d], q0);  atomicAdd(&sd2[d + 1], q1);
                    }
                }
            }
            #pragma unroll
            for (int a = 0; a < 2; a++)
                #pragma unroll
                for (int b = 0; b < 8; b++)
                    #pragma unroll
                    for (int c2 = 0; c2 < 4; c2++) acc[a][b][c2] = 0.f;
        }
    }

    __syncthreads();
    if (dostats && tid < 64) {
        atomicAdd(&g_sumK[tid], sd[tid]);
        atomicAdd(&g_sumK2[tid], sd2[tid]);
    }
}

// ---------------- fold BN stats into per-d affine constants ------------------
__global__ void finalize_kernel(const float* __restrict__ Wq,
                                const float* __restrict__ gammaQ,
                                const float* __restrict__ betaQ,
                                const float* __restrict__ gammaK,
                                const float* __restrict__ betaK)
{
    int d = threadIdx.x;
    if (d >= 64) return;
    const float invB = 1.f / 65536.f;

    float w[4];
    #pragma unroll
    for (int c = 0; c < 4; c++) w[c] = Wq[d * 4 + c];

    float mQ = 0.f;
    #pragma unroll
    for (int c = 0; c < 4; c++) mQ += (g_cmd[c] * invB) * w[c];
    float eq2 = 0.f;
    #pragma unroll
    for (int c1 = 0; c1 < 4; c1++)
        #pragma unroll
        for (int c2 = 0; c2 < 4; c2++)
            eq2 += w[c1] * w[c2] * g_cmd[4 + c1 * 4 + c2];
    eq2 *= invB;
    float vQ = eq2 - mQ * mQ;
    float gq = gammaQ[d] / sqrtf(vQ + EPS);
    g_cst[d]      = gq;
    g_cst[64 + d] = betaQ[d] - mQ * gq;

    const float invBF = 1.f / (65536.f * 32.f);
    float mK = g_sumK[d] * invBF;
    float vK = g_sumK2[d] * invBF - mK * mK;
    float aK = gammaK[d] / sqrtf(vK + EPS);
    g_cst[128 + d] = aK;
    g_cst[192 + d] = betaK[d] - mK * aK;
}

// ---------------- attention: 1 warp per batch row, V prefetched ---------------
// lane l owns d-pair {2l, 2l+1}. K reads half2 at b*2048 + f*64 + 2l (coalesced
// 128B per f). V words prefetched into registers BEFORE the butterfly/softmax
// so both memory streams are in flight through the serial shuffle window.
__global__ __launch_bounds__(256) void attn_kernel(
    const float* __restrict__ command, const float* __restrict__ Wq,
    float* __restrict__ out)
{
    const int w    = threadIdx.x >> 5;
    const int lane = threadIdx.x & 31;
    const int b    = blockIdx.x * 8 + w;

    float4 c4 = *(const float4*)(command + (size_t)b * 4);
    const int d0 = 2 * lane, d1 = 2 * lane + 1;

    float q0 = c4.x * Wq[d0 * 4 + 0] + c4.y * Wq[d0 * 4 + 1] +
               c4.z * Wq[d0 * 4 + 2] + c4.w * Wq[d0 * 4 + 3];
    float q1 = c4.x * Wq[d1 * 4 + 0] + c4.y * Wq[d1 * 4 + 1] +
               c4.z * Wq[d1 * 4 + 2] + c4.w * Wq[d1 * 4 + 3];
    float qn0 = q0 * g_cst[d0] + g_cst[64 + d0];
    float qn1 = q1 * g_cst[d1] + g_cst[64 + d1];

    float qa0 = qn0 * g_cst[128 + d0];
    float qa1 = qn1 * g_cst[128 + d1];
    float qc  = qn0 * g_cst[192 + d0] + qn1 * g_cst[192 + d1];
    #pragma unroll
    for (int o = 16; o; o >>= 1) qc += __shfl_xor_sync(0xffffffffu, qc, o);

    // K partials (coalesced 128B per f)
    const __half2* Kr = (const __half2*)(g_Kh + (size_t)b * 2048) + lane;
    float p[32];
    #pragma unroll
    for (int f = 0; f < 32; f++) {
        float2 kf = __half22float2(Kr[f * 32]);
        p[f] = qa0 * kf.x + qa1 * kf.y;
    }

    // prefetch all V words (register-resident) before serial shuffle phase
    const __half2* Vr = (const __half2*)(g_Vh + (size_t)b * 2048) + lane;
    __half2 vbuf[32];
    #pragma unroll
    for (int f = 0; f < 32; f++) vbuf[f] = Vr[f * 32];

    // butterfly transpose-reduce: lane l ends with full logit for f = l
    #pragma unroll
    for (int o = 16; o >= 1; o >>= 1) {
        #pragma unroll
        for (int j = 0; j < o; j++) {
            bool hi = (lane & o) != 0;
            float keep = hi ? p[j + o] : p[j];
            float send = hi ? p[j] : p[j + o];
            p[j] = keep + __shfl_xor_sync(0xffffffffu, send, o);
        }
    }
    float logit = (p[0] + qc) * 0.125f;   // 1/sqrt(64)

    float mx = logit;
    #pragma unroll
    for (int o = 16; o; o >>= 1) mx = fmaxf(mx, __shfl_xor_sync(0xffffffffu, mx, o));
    float e = __expf(logit - mx);
    float den = e;
    #pragma unroll
    for (int o = 16; o; o >>= 1) den += __shfl_xor_sync(0xffffffffu, den, o);
    float a = e / den;

    float s0 = 0.f, s1 = 0.f;
    #pragma unroll
    for (int f = 0; f < 32; f++) {
        float af = __shfl_sync(0xffffffffu, a, f);
        float2 vf = __half22float2(vbuf[f]);
        s0 += af * vf.x;
        s1 += af * vf.y;
    }
    *(float2*)(out + (size_t)b * 64 + 2 * lane) = make_float2(s0, s1);
}

// ---------------- launch ------------------------------------------------------
extern "C" void kernel_launch(void* const* d_in, const int* in_sizes, int n_in,
                              void* d_out, int out_size)
{
    const float* feature = (const float*)d_in[0];
    const float* hidden  = (const float*)d_in[1];
    const float* command = (const float*)d_in[2];
    const float* Wq      = (const float*)d_in[3];
    const float* Wkz     = (const float*)d_in[4];
    const float* Wkh     = (const float*)d_in[5];
    const float* Wvz     = (const float*)d_in[6];
    const float* Wvh     = (const float*)d_in[7];
    const float* gammaQ  = (const float*)d_in[8];
    const float* betaQ   = (const float*)d_in[9];
    const float* gammaK  = (const float*)d_in[10];
    const float* betaK   = (const float*)d_in[11];
    float* out = (float*)d_out;

    cudaFuncSetAttribute(gemm_mma_kernel,
                         cudaFuncAttributeMaxDynamicSharedMemorySize, GEMM_SMEM);

    split_kernel<<<33792, 256>>>(feature, hidden, Wkz, Wkh, Wvz, Wvh);
    cmd_stats_kernel<<<128, 256>>>(command);
    gemm_mma_kernel<<<1024, 512, GEMM_SMEM>>>();
    finalize_kernel<<<1, 64>>>(Wq, gammaQ, betaQ, gammaK, betaK);
    attn_kernel<<<B_TOT / 8, 256>>>(command, Wq, out);
}